// round 1
// baseline (speedup 1.0000x reference)
#include <cuda_runtime.h>
#include <cstdint>

#define N_NODES 50000
#define N_EDGES 800000
#define D 64

// Scratch (device globals — no allocation allowed)
__device__ float g_Sn[N_NODES * D];   // sum of nfeats[src] per dst
__device__ float g_Se[N_NODES * D];   // sum of efeats per dst
__device__ float g_deg[N_NODES];      // in-degree (float)

// ---------------------------------------------------------------------------
// Kernel 1: zero the scratch accumulators
// ---------------------------------------------------------------------------
__global__ void zero_kernel() {
    int tid = blockIdx.x * blockDim.x + threadIdx.x;
    int stride = gridDim.x * blockDim.x;
    float4 z4 = make_float4(0.f, 0.f, 0.f, 0.f);
    int n4 = (N_NODES * D) / 4;
    for (int i = tid; i < n4; i += stride) {
        ((float4*)g_Sn)[i] = z4;
        ((float4*)g_Se)[i] = z4;
    }
    int d4 = N_NODES / 4;
    for (int i = tid; i < d4; i += stride) ((float4*)g_deg)[i] = z4;
}

// ---------------------------------------------------------------------------
// Kernel 2: edge scatter. One warp per edge.
// lanes 0..15: nfeats[src] float4 -> red.add into g_Sn[dst]
// lanes 16..31: efeats[e] float4 -> red.add into g_Se[dst]
// ---------------------------------------------------------------------------
__global__ void edge_kernel(const float* __restrict__ nfeats,
                            const float* __restrict__ efeats,
                            const int* __restrict__ src,
                            const int* __restrict__ dst, int E) {
    int e = (blockIdx.x * blockDim.x + threadIdx.x) >> 5;
    int lane = threadIdx.x & 31;
    if (e >= E) return;
    int s = __ldg(src + e);
    int d = __ldg(dst + e);
    float4 v;
    float* p;
    int q = lane & 15;
    if (lane < 16) {
        v = ((const float4*)(nfeats + (size_t)s * D))[q];
        p = g_Sn + (size_t)d * D + q * 4;
    } else {
        v = ((const float4*)(efeats + (size_t)e * D))[q];
        p = g_Se + (size_t)d * D + q * 4;
    }
    asm volatile("red.global.add.v4.f32 [%0], {%1,%2,%3,%4};"
                 :: "l"(p), "f"(v.x), "f"(v.y), "f"(v.z), "f"(v.w)
                 : "memory");
    if (lane == 0) atomicAdd(g_deg + d, 1.0f);
}

// ---------------------------------------------------------------------------
// Kernel 3: node update (fused msg-GEMM + mean + apply-GEMM + relu).
// Block = 256 threads = 8 warps, 8 nodes per warp, 64 nodes per block.
// Weights staged transposed in SMEM: WT[k][o]. Per-warp z buffer staged
// TRANSPOSED: zT[k][node] (row stride ZSTRIDE) so node-pairs load as LDS.64
// broadcasts and accumulate via packed fma.rn.f32x2 (FFMA2).
// Lane handles outputs o = lane and o = lane+32 across 8 nodes (4 node-pairs).
// ---------------------------------------------------------------------------
#define ZSTRIDE 10          // even (8B-aligned pairs), low bank conflict on setup
#define WPB 8               // warps per block
#define NPW 8               // nodes per warp
#define NPB (WPB * NPW)     // 64 nodes per block

#define PACK2(dst, f) asm("mov.b64 %0, {%1,%1};" : "=l"(dst) : "r"(__float_as_uint(f)))
#define UNPACK2(lo, hi, src) asm("mov.b64 {%0,%1}, %2;" : "=r"(lo), "=r"(hi) : "l"(src))
#define FMA2(acc, a, b) asm("fma.rn.f32x2 %0, %1, %2, %0;" : "+l"(acc) : "l"(a), "l"(b))

__global__ __launch_bounds__(256, 2)
void node_kernel(const float* __restrict__ nfeats,
                 const float* __restrict__ W_msg, const float* __restrict__ b_msg,
                 const float* __restrict__ W_apply, const float* __restrict__ b_apply,
                 float* __restrict__ out) {
    extern __shared__ float sm[];
    float* WmT = sm;                      // [128][64]
    float* WaT = sm + 128 * 64;           // [128][64]
    float* zb = sm + 2 * 128 * 64;        // WPB * [128][ZSTRIDE]

    int tid = threadIdx.x;
    int lane = tid & 31;
    int wid = tid >> 5;

    // Stage transposed weights (one-time per block)
    for (int i = tid; i < 64 * 128; i += 256) {
        int o = i >> 7, k = i & 127;
        WmT[k * 64 + o] = W_msg[i];
        WaT[k * 64 + o] = W_apply[i];
    }
    __syncthreads();

    float* z = zb + wid * (128 * ZSTRIDE);
    int base = blockIdx.x * NPB + wid * NPW;

    // ---- Phase A setup: zT rows 0..63 = Sn, rows 64..127 = Se ----
    #pragma unroll
    for (int j = 0; j < NPW; j++) {
        int v = base + j;
        if (v >= N_NODES) v = N_NODES - 1;
        const float* sn = g_Sn + (size_t)v * D;
        const float* se = g_Se + (size_t)v * D;
        z[(lane)      * ZSTRIDE + j] = sn[lane];
        z[(lane + 32) * ZSTRIDE + j] = sn[lane + 32];
        z[(lane + 64) * ZSTRIDE + j] = se[lane];
        z[(lane + 96) * ZSTRIDE + j] = se[lane + 32];
    }
    __syncwarp();

    // ---- Phase A GEMM: acc[g][p] = packed (node 2p, node 2p+1) for out o_g ----
    unsigned long long acc[2][4];
    #pragma unroll
    for (int g = 0; g < 2; g++)
        #pragma unroll
        for (int p = 0; p < 4; p++) acc[g][p] = 0ull;

    #pragma unroll 4
    for (int k = 0; k < 128; k++) {
        float w0 = WmT[k * 64 + lane];
        float w1 = WmT[k * 64 + lane + 32];
        unsigned long long w0p, w1p;
        PACK2(w0p, w0);
        PACK2(w1p, w1);
        const unsigned long long* zr = (const unsigned long long*)(z + k * ZSTRIDE);
        #pragma unroll
        for (int p = 0; p < 4; p++) {
            unsigned long long s2 = zr[p];
            FMA2(acc[0][p], w0p, s2);
            FMA2(acc[1][p], w1p, s2);
        }
    }
    __syncwarp();

    // ---- h_neigh + rebuild z for Phase B: rows 0..63 = nfeats, 64..127 = hn ----
    float bm0 = b_msg[lane], bm1 = b_msg[lane + 32];
    #pragma unroll
    for (int p = 0; p < 4; p++) {
        int v0 = base + 2 * p, v1 = base + 2 * p + 1;
        int c0 = v0 < N_NODES ? v0 : N_NODES - 1;
        int c1 = v1 < N_NODES ? v1 : N_NODES - 1;
        float d0 = g_deg[c0];
        float d1 = g_deg[c1];
        float i0 = d0 > 0.f ? 1.f / d0 : 0.f;
        float i1 = d1 > 0.f ? 1.f / d1 : 0.f;
        unsigned ux, uy;
        UNPACK2(ux, uy, acc[0][p]);
        float a0x = __uint_as_float(ux), a0y = __uint_as_float(uy);
        UNPACK2(ux, uy, acc[1][p]);
        float a1x = __uint_as_float(ux), a1y = __uint_as_float(uy);
        // hn(v, o) = deg>0 ? acc/deg + b_msg[o] : 0
        z[(64 + lane) * ZSTRIDE + 2 * p]     = d0 > 0.f ? a0x * i0 + bm0 : 0.f;
        z[(64 + lane) * ZSTRIDE + 2 * p + 1] = d1 > 0.f ? a0y * i1 + bm0 : 0.f;
        z[(96 + lane) * ZSTRIDE + 2 * p]     = d0 > 0.f ? a1x * i0 + bm1 : 0.f;
        z[(96 + lane) * ZSTRIDE + 2 * p + 1] = d1 > 0.f ? a1y * i1 + bm1 : 0.f;
    }
    #pragma unroll
    for (int j = 0; j < NPW; j++) {
        int v = base + j;
        if (v >= N_NODES) v = N_NODES - 1;
        const float* nf = nfeats + (size_t)v * D;
        z[(lane)      * ZSTRIDE + j] = nf[lane];
        z[(lane + 32) * ZSTRIDE + j] = nf[lane + 32];
    }
    __syncwarp();

    // ---- Phase B GEMM ----
    #pragma unroll
    for (int g = 0; g < 2; g++)
        #pragma unroll
        for (int p = 0; p < 4; p++) acc[g][p] = 0ull;

    #pragma unroll 4
    for (int k = 0; k < 128; k++) {
        float w0 = WaT[k * 64 + lane];
        float w1 = WaT[k * 64 + lane + 32];
        unsigned long long w0p, w1p;
        PACK2(w0p, w0);
        PACK2(w1p, w1);
        const unsigned long long* zr = (const unsigned long long*)(z + k * ZSTRIDE);
        #pragma unroll
        for (int p = 0; p < 4; p++) {
            unsigned long long s2 = zr[p];
            FMA2(acc[0][p], w0p, s2);
            FMA2(acc[1][p], w1p, s2);
        }
    }

    // ---- Epilogue: bias + relu + store ----
    float ba0 = b_apply[lane], ba1 = b_apply[lane + 32];
    #pragma unroll
    for (int p = 0; p < 4; p++) {
        int v0 = base + 2 * p, v1 = base + 2 * p + 1;
        unsigned ux, uy;
        UNPACK2(ux, uy, acc[0][p]);
        float a0x = __uint_as_float(ux), a0y = __uint_as_float(uy);
        UNPACK2(ux, uy, acc[1][p]);
        float a1x = __uint_as_float(ux), a1y = __uint_as_float(uy);
        if (v0 < N_NODES) {
            out[(size_t)v0 * D + lane]      = fmaxf(a0x + ba0, 0.f);
            out[(size_t)v0 * D + lane + 32] = fmaxf(a1x + ba1, 0.f);
        }
        if (v1 < N_NODES) {
            out[(size_t)v1 * D + lane]      = fmaxf(a0y + ba0, 0.f);
            out[(size_t)v1 * D + lane + 32] = fmaxf(a1y + ba1, 0.f);
        }
    }
}

// ---------------------------------------------------------------------------
// Launch
// ---------------------------------------------------------------------------
#define NODE_SMEM ((2 * 128 * 64 + WPB * 128 * ZSTRIDE) * (int)sizeof(float))

extern "C" void kernel_launch(void* const* d_in, const int* in_sizes, int n_in,
                              void* d_out, int out_size) {
    const float* nfeats  = (const float*)d_in[0];
    const float* efeats  = (const float*)d_in[1];
    const int*   src     = (const int*)d_in[2];
    const int*   dst     = (const int*)d_in[3];
    const float* W_msg   = (const float*)d_in[4];
    const float* b_msg   = (const float*)d_in[5];
    const float* W_apply = (const float*)d_in[6];
    const float* b_apply = (const float*)d_in[7];
    float* out = (float*)d_out;
    int E = in_sizes[2];

    cudaFuncSetAttribute(node_kernel, cudaFuncAttributeMaxDynamicSharedMemorySize,
                         NODE_SMEM);

    zero_kernel<<<1024, 256>>>();
    int eblocks = (E * 32 + 255) / 256;
    edge_kernel<<<eblocks, 256>>>(nfeats, efeats, src, dst, E);
    int nblocks = (N_NODES + NPB - 1) / NPB;
    node_kernel<<<nblocks, 256, NODE_SMEM>>>(nfeats, W_msg, b_msg, W_apply,
                                             b_apply, out);
}

// round 2
// speedup vs baseline: 1.2891x; 1.2891x over previous
#include <cuda_runtime.h>
#include <cstdint>

#define N_NODES 50000
#define MAXE    800000
#define D       64

// ---- scratch (device globals; no allocation allowed) ----
__device__ float g_Sn[N_NODES * D];   // sum of nfeats[src] per dst
__device__ float g_Se[N_NODES * D];   // sum of efeats per dst
__device__ int   g_count[N_NODES];    // in-degree
__device__ int   g_off[N_NODES];      // CSR offsets (exclusive scan of count)
__device__ int   g_cursor[N_NODES];   // scatter cursors
__device__ int2  g_edges[MAXE];       // permuted (edge_id, src) records

// ---------------------------------------------------------------------------
// K1: zero degree counters
// ---------------------------------------------------------------------------
__global__ void zero_counts() {
    int i = blockIdx.x * blockDim.x + threadIdx.x;
    if (i < N_NODES) g_count[i] = 0;
}

// ---------------------------------------------------------------------------
// K2: histogram of dst
// ---------------------------------------------------------------------------
__global__ void hist_kernel(const int* __restrict__ dst, int E) {
    int e = blockIdx.x * blockDim.x + threadIdx.x;
    if (e < E) atomicAdd(&g_count[dst[e]], 1);
}

// ---------------------------------------------------------------------------
// K3: single-block exclusive scan of 50K counts -> g_off, g_cursor
// 1024 threads, ~49 elements each, two passes (counts are L2-resident).
// ---------------------------------------------------------------------------
__global__ void scan_kernel() {
    __shared__ int warp_tot[32];
    int t = threadIdx.x;
    int lane = t & 31, w = t >> 5;
    const int CHUNK = (N_NODES + 1023) / 1024;
    int begin = t * CHUNK;
    int end = begin + CHUNK;
    if (end > N_NODES) end = N_NODES;
    if (begin > N_NODES) begin = N_NODES;

    int s = 0;
    for (int i = begin; i < end; i++) s += g_count[i];

    // intra-warp inclusive scan of thread totals
    int pre = s;
    #pragma unroll
    for (int d = 1; d < 32; d <<= 1) {
        int v = __shfl_up_sync(0xffffffffu, pre, d);
        if (lane >= d) pre += v;
    }
    if (lane == 31) warp_tot[w] = pre;
    __syncthreads();
    if (w == 0) {
        int v = warp_tot[lane];
        #pragma unroll
        for (int d = 1; d < 32; d <<= 1) {
            int u = __shfl_up_sync(0xffffffffu, v, d);
            if (lane >= d) v += u;
        }
        warp_tot[lane] = v;  // inclusive warp totals
    }
    __syncthreads();
    int base = (w > 0 ? warp_tot[w - 1] : 0) + (pre - s);  // thread-exclusive
    int run = base;
    for (int i = begin; i < end; i++) {
        int c = g_count[i];
        g_off[i] = run;
        g_cursor[i] = run;
        run += c;
    }
}

// ---------------------------------------------------------------------------
// K4: scatter (edge_id, src) into dst-sorted slots
// ---------------------------------------------------------------------------
__global__ void scatter_kernel(const int* __restrict__ src,
                               const int* __restrict__ dst, int E) {
    int e = blockIdx.x * blockDim.x + threadIdx.x;
    if (e >= E) return;
    int d = dst[e];
    int slot = atomicAdd(&g_cursor[d], 1);
    g_edges[slot] = make_int2(e, src[e]);
}

// ---------------------------------------------------------------------------
// K5: atomic-free gather-sum. One warp per node.
// lanes 0..15: chunk q of sum(nfeats[src]); lanes 16..31: chunk q of sum(efeats)
// Coalesced 256B loads per half-warp; register accumulation; float4 store.
// ---------------------------------------------------------------------------
__global__ __launch_bounds__(256)
void gather_kernel(const float* __restrict__ nfeats,
                   const float* __restrict__ efeats) {
    int v = (blockIdx.x * blockDim.x + threadIdx.x) >> 5;
    int lane = threadIdx.x & 31;
    if (v >= N_NODES) return;
    int start = g_off[v];
    int cnt = g_count[v];
    int end = start + cnt;
    int q = lane & 15;
    bool isN = lane < 16;

    float4 acc = make_float4(0.f, 0.f, 0.f, 0.f);
    int i = start;
    for (; i + 1 < end; i += 2) {
        int2 e0 = g_edges[i];
        int2 e1 = g_edges[i + 1];
        const float4* p0 = (const float4*)(isN ? nfeats + (size_t)e0.y * D
                                               : efeats + (size_t)e0.x * D) + q;
        const float4* p1 = (const float4*)(isN ? nfeats + (size_t)e1.y * D
                                               : efeats + (size_t)e1.x * D) + q;
        float4 a = __ldg(p0);
        float4 b = __ldg(p1);
        acc.x += a.x; acc.y += a.y; acc.z += a.z; acc.w += a.w;
        acc.x += b.x; acc.y += b.y; acc.z += b.z; acc.w += b.w;
    }
    if (i < end) {
        int2 e0 = g_edges[i];
        const float4* p0 = (const float4*)(isN ? nfeats + (size_t)e0.y * D
                                               : efeats + (size_t)e0.x * D) + q;
        float4 a = __ldg(p0);
        acc.x += a.x; acc.y += a.y; acc.z += a.z; acc.w += a.w;
    }
    float* outp = (isN ? g_Sn : g_Se) + (size_t)v * D + q * 4;
    *(float4*)outp = acc;
}

// ---------------------------------------------------------------------------
// K6: node update (fused msg-GEMM + mean + apply-GEMM + relu). Unchanged from
// R1 except deg comes from g_count (int).
// ---------------------------------------------------------------------------
#define ZSTRIDE 10
#define WPB 8
#define NPW 8
#define NPB (WPB * NPW)

#define PACK2(dst, f) asm("mov.b64 %0, {%1,%1};" : "=l"(dst) : "r"(__float_as_uint(f)))
#define UNPACK2(lo, hi, src) asm("mov.b64 {%0,%1}, %2;" : "=r"(lo), "=r"(hi) : "l"(src))
#define FMA2(acc, a, b) asm("fma.rn.f32x2 %0, %1, %2, %0;" : "+l"(acc) : "l"(a), "l"(b))

__global__ __launch_bounds__(256, 2)
void node_kernel(const float* __restrict__ nfeats,
                 const float* __restrict__ W_msg, const float* __restrict__ b_msg,
                 const float* __restrict__ W_apply, const float* __restrict__ b_apply,
                 float* __restrict__ out) {
    extern __shared__ float sm[];
    float* WmT = sm;                      // [128][64]
    float* WaT = sm + 128 * 64;           // [128][64]
    float* zb = sm + 2 * 128 * 64;        // WPB * [128][ZSTRIDE]

    int tid = threadIdx.x;
    int lane = tid & 31;
    int wid = tid >> 5;

    for (int i = tid; i < 64 * 128; i += 256) {
        int o = i >> 7, k = i & 127;
        WmT[k * 64 + o] = W_msg[i];
        WaT[k * 64 + o] = W_apply[i];
    }
    __syncthreads();

    float* z = zb + wid * (128 * ZSTRIDE);
    int base = blockIdx.x * NPB + wid * NPW;

    // Phase A setup: rows 0..63 = Sn, rows 64..127 = Se
    #pragma unroll
    for (int j = 0; j < NPW; j++) {
        int v = base + j;
        if (v >= N_NODES) v = N_NODES - 1;
        const float* sn = g_Sn + (size_t)v * D;
        const float* se = g_Se + (size_t)v * D;
        z[(lane)      * ZSTRIDE + j] = sn[lane];
        z[(lane + 32) * ZSTRIDE + j] = sn[lane + 32];
        z[(lane + 64) * ZSTRIDE + j] = se[lane];
        z[(lane + 96) * ZSTRIDE + j] = se[lane + 32];
    }
    __syncwarp();

    unsigned long long acc[2][4];
    #pragma unroll
    for (int g = 0; g < 2; g++)
        #pragma unroll
        for (int p = 0; p < 4; p++) acc[g][p] = 0ull;

    #pragma unroll 4
    for (int k = 0; k < 128; k++) {
        float w0 = WmT[k * 64 + lane];
        float w1 = WmT[k * 64 + lane + 32];
        unsigned long long w0p, w1p;
        PACK2(w0p, w0);
        PACK2(w1p, w1);
        const unsigned long long* zr = (const unsigned long long*)(z + k * ZSTRIDE);
        #pragma unroll
        for (int p = 0; p < 4; p++) {
            unsigned long long s2 = zr[p];
            FMA2(acc[0][p], w0p, s2);
            FMA2(acc[1][p], w1p, s2);
        }
    }
    __syncwarp();

    // h_neigh + rebuild z for Phase B
    float bm0 = b_msg[lane], bm1 = b_msg[lane + 32];
    #pragma unroll
    for (int p = 0; p < 4; p++) {
        int v0 = base + 2 * p, v1 = base + 2 * p + 1;
        int c0 = v0 < N_NODES ? v0 : N_NODES - 1;
        int c1 = v1 < N_NODES ? v1 : N_NODES - 1;
        float d0 = (float)g_count[c0];
        float d1 = (float)g_count[c1];
        float i0 = d0 > 0.f ? 1.f / d0 : 0.f;
        float i1 = d1 > 0.f ? 1.f / d1 : 0.f;
        unsigned ux, uy;
        UNPACK2(ux, uy, acc[0][p]);
        float a0x = __uint_as_float(ux), a0y = __uint_as_float(uy);
        UNPACK2(ux, uy, acc[1][p]);
        float a1x = __uint_as_float(ux), a1y = __uint_as_float(uy);
        z[(64 + lane) * ZSTRIDE + 2 * p]     = d0 > 0.f ? a0x * i0 + bm0 : 0.f;
        z[(64 + lane) * ZSTRIDE + 2 * p + 1] = d1 > 0.f ? a0y * i1 + bm0 : 0.f;
        z[(96 + lane) * ZSTRIDE + 2 * p]     = d0 > 0.f ? a1x * i0 + bm1 : 0.f;
        z[(96 + lane) * ZSTRIDE + 2 * p + 1] = d1 > 0.f ? a1y * i1 + bm1 : 0.f;
    }
    #pragma unroll
    for (int j = 0; j < NPW; j++) {
        int v = base + j;
        if (v >= N_NODES) v = N_NODES - 1;
        const float* nf = nfeats + (size_t)v * D;
        z[(lane)      * ZSTRIDE + j] = nf[lane];
        z[(lane + 32) * ZSTRIDE + j] = nf[lane + 32];
    }
    __syncwarp();

    #pragma unroll
    for (int g = 0; g < 2; g++)
        #pragma unroll
        for (int p = 0; p < 4; p++) acc[g][p] = 0ull;

    #pragma unroll 4
    for (int k = 0; k < 128; k++) {
        float w0 = WaT[k * 64 + lane];
        float w1 = WaT[k * 64 + lane + 32];
        unsigned long long w0p, w1p;
        PACK2(w0p, w0);
        PACK2(w1p, w1);
        const unsigned long long* zr = (const unsigned long long*)(z + k * ZSTRIDE);
        #pragma unroll
        for (int p = 0; p < 4; p++) {
            unsigned long long s2 = zr[p];
            FMA2(acc[0][p], w0p, s2);
            FMA2(acc[1][p], w1p, s2);
        }
    }

    float ba0 = b_apply[lane], ba1 = b_apply[lane + 32];
    #pragma unroll
    for (int p = 0; p < 4; p++) {
        int v0 = base + 2 * p, v1 = base + 2 * p + 1;
        unsigned ux, uy;
        UNPACK2(ux, uy, acc[0][p]);
        float a0x = __uint_as_float(ux), a0y = __uint_as_float(uy);
        UNPACK2(ux, uy, acc[1][p]);
        float a1x = __uint_as_float(ux), a1y = __uint_as_float(uy);
        if (v0 < N_NODES) {
            out[(size_t)v0 * D + lane]      = fmaxf(a0x + ba0, 0.f);
            out[(size_t)v0 * D + lane + 32] = fmaxf(a1x + ba1, 0.f);
        }
        if (v1 < N_NODES) {
            out[(size_t)v1 * D + lane]      = fmaxf(a0y + ba0, 0.f);
            out[(size_t)v1 * D + lane + 32] = fmaxf(a1y + ba1, 0.f);
        }
    }
}

// ---------------------------------------------------------------------------
#define NODE_SMEM ((2 * 128 * 64 + WPB * 128 * ZSTRIDE) * (int)sizeof(float))

extern "C" void kernel_launch(void* const* d_in, const int* in_sizes, int n_in,
                              void* d_out, int out_size) {
    const float* nfeats  = (const float*)d_in[0];
    const float* efeats  = (const float*)d_in[1];
    const int*   src     = (const int*)d_in[2];
    const int*   dst     = (const int*)d_in[3];
    const float* W_msg   = (const float*)d_in[4];
    const float* b_msg   = (const float*)d_in[5];
    const float* W_apply = (const float*)d_in[6];
    const float* b_apply = (const float*)d_in[7];
    float* out = (float*)d_out;
    int E = in_sizes[2];

    cudaFuncSetAttribute(node_kernel, cudaFuncAttributeMaxDynamicSharedMemorySize,
                         NODE_SMEM);

    zero_counts<<<(N_NODES + 255) / 256, 256>>>();
    hist_kernel<<<(E + 255) / 256, 256>>>(dst, E);
    scan_kernel<<<1, 1024>>>();
    scatter_kernel<<<(E + 255) / 256, 256>>>(src, dst, E);
    int gblocks = (N_NODES * 32 + 255) / 256;
    gather_kernel<<<gblocks, 256>>>(nfeats, efeats);
    int nblocks = (N_NODES + NPB - 1) / NPB;
    node_kernel<<<nblocks, 256, NODE_SMEM>>>(nfeats, W_msg, b_msg, W_apply,
                                             b_apply, out);
}

// round 3
// speedup vs baseline: 1.4301x; 1.1094x over previous
#include <cuda_runtime.h>
#include <cstdint>

#define N_NODES 50000
#define MAXE    800000
#define D       64

// ---- scratch (device globals; no allocation allowed) ----
__device__ float g_Sn[N_NODES * D];   // sum of nfeats[src] per dst
__device__ float g_Se[N_NODES * D];   // sum of efeats per dst
__device__ int   g_count[N_NODES];    // in-degree
__device__ int   g_off[N_NODES];      // CSR offsets (exclusive scan)
__device__ int   g_rank[MAXE];        // within-dst rank of each edge
__device__ int2  g_edges[MAXE];       // dst-sorted (edge_id, src) records

// ---------------------------------------------------------------------------
// K1: zero degree counters
// ---------------------------------------------------------------------------
__global__ void zero_counts() {
    int i = blockIdx.x * blockDim.x + threadIdx.x;
    if (i < N_NODES) g_count[i] = 0;
}

// ---------------------------------------------------------------------------
// K2: histogram of dst; the atomic's return value is the edge's rank
// ---------------------------------------------------------------------------
__global__ void hist_kernel(const int* __restrict__ dst, int E) {
    int e = blockIdx.x * blockDim.x + threadIdx.x;
    if (e < E) g_rank[e] = atomicAdd(&g_count[dst[e]], 1);
}

// ---------------------------------------------------------------------------
// K3: single-block exclusive scan of 50K counts -> g_off
// ---------------------------------------------------------------------------
__global__ void scan_kernel() {
    __shared__ int warp_tot[32];
    int t = threadIdx.x;
    int lane = t & 31, w = t >> 5;
    const int CHUNK = (N_NODES + 1023) / 1024;
    int begin = t * CHUNK;
    int end = begin + CHUNK;
    if (end > N_NODES) end = N_NODES;
    if (begin > N_NODES) begin = N_NODES;

    int s = 0;
    for (int i = begin; i < end; i++) s += g_count[i];

    int pre = s;
    #pragma unroll
    for (int d = 1; d < 32; d <<= 1) {
        int v = __shfl_up_sync(0xffffffffu, pre, d);
        if (lane >= d) pre += v;
    }
    if (lane == 31) warp_tot[w] = pre;
    __syncthreads();
    if (w == 0) {
        int v = warp_tot[lane];
        #pragma unroll
        for (int d = 1; d < 32; d <<= 1) {
            int u = __shfl_up_sync(0xffffffffu, v, d);
            if (lane >= d) v += u;
        }
        warp_tot[lane] = v;
    }
    __syncthreads();
    int base = (w > 0 ? warp_tot[w - 1] : 0) + (pre - s);
    int run = base;
    for (int i = begin; i < end; i++) {
        int c = g_count[i];
        g_off[i] = run;
        run += c;
    }
}

// ---------------------------------------------------------------------------
// K4: atomic-free scatter: slot = off[dst] + rank[e]
// ---------------------------------------------------------------------------
__global__ void scatter_kernel(const int* __restrict__ src,
                               const int* __restrict__ dst, int E) {
    int e = blockIdx.x * blockDim.x + threadIdx.x;
    if (e >= E) return;
    int d = dst[e];
    int slot = g_off[d] + g_rank[e];
    g_edges[slot] = make_int2(e, src[e]);
}

// ---------------------------------------------------------------------------
// K5: atomic-free gather-sum. One warp per node.
// Edge records bulk-loaded coalesced into SMEM, feature-load addresses come
// from broadcast LDS (independent of any in-flight LDG) -> MLP ~8.
// lanes 0..15: chunk q of sum(nfeats[src]); lanes 16..31: chunk q of sum(efeats)
// ---------------------------------------------------------------------------
#define GW 8   // warps per block
__global__ __launch_bounds__(256)
void gather_kernel(const float* __restrict__ nfeats,
                   const float* __restrict__ efeats) {
    __shared__ int2 srec[GW][32];
    int v = (blockIdx.x * blockDim.x + threadIdx.x) >> 5;
    int lane = threadIdx.x & 31;
    int w = threadIdx.x >> 5;
    if (v >= N_NODES) return;
    int start = g_off[v];
    int cnt = g_count[v];
    int q = lane & 15;
    bool isN = lane < 16;
    const float* fbase = isN ? nfeats : efeats;

    float4 acc0 = make_float4(0.f, 0.f, 0.f, 0.f);
    float4 acc1 = make_float4(0.f, 0.f, 0.f, 0.f);

    for (int base = 0; base < cnt; base += 32) {
        int n = cnt - base;
        if (n > 32) n = 32;
        if (lane < n) srec[w][lane] = g_edges[start + base + lane];
        __syncwarp();
        int j = 0;
        for (; j + 4 <= n; j += 4) {
            int2 r0 = srec[w][j];
            int2 r1 = srec[w][j + 1];
            int2 r2 = srec[w][j + 2];
            int2 r3 = srec[w][j + 3];
            float4 a = __ldg((const float4*)(fbase + (size_t)(isN ? r0.y : r0.x) * D) + q);
            float4 b = __ldg((const float4*)(fbase + (size_t)(isN ? r1.y : r1.x) * D) + q);
            float4 c = __ldg((const float4*)(fbase + (size_t)(isN ? r2.y : r2.x) * D) + q);
            float4 d = __ldg((const float4*)(fbase + (size_t)(isN ? r3.y : r3.x) * D) + q);
            acc0.x += a.x; acc0.y += a.y; acc0.z += a.z; acc0.w += a.w;
            acc1.x += b.x; acc1.y += b.y; acc1.z += b.z; acc1.w += b.w;
            acc0.x += c.x; acc0.y += c.y; acc0.z += c.z; acc0.w += c.w;
            acc1.x += d.x; acc1.y += d.y; acc1.z += d.z; acc1.w += d.w;
        }
        for (; j < n; j++) {
            int2 r0 = srec[w][j];
            float4 a = __ldg((const float4*)(fbase + (size_t)(isN ? r0.y : r0.x) * D) + q);
            acc0.x += a.x; acc0.y += a.y; acc0.z += a.z; acc0.w += a.w;
        }
        __syncwarp();
    }
    acc0.x += acc1.x; acc0.y += acc1.y; acc0.z += acc1.z; acc0.w += acc1.w;
    float* outp = (isN ? g_Sn : g_Se) + (size_t)v * D + q * 4;
    *(float4*)outp = acc0;
}

// ---------------------------------------------------------------------------
// K6: node update (fused msg-GEMM + mean + apply-GEMM + relu).
// ---------------------------------------------------------------------------
#define ZSTRIDE 10
#define WPB 8
#define NPW 8
#define NPB (WPB * NPW)

#define PACK2(dst, f) asm("mov.b64 %0, {%1,%1};" : "=l"(dst) : "r"(__float_as_uint(f)))
#define UNPACK2(lo, hi, src) asm("mov.b64 {%0,%1}, %2;" : "=r"(lo), "=r"(hi) : "l"(src))
#define FMA2(acc, a, b) asm("fma.rn.f32x2 %0, %1, %2, %0;" : "+l"(acc) : "l"(a), "l"(b))

__global__ __launch_bounds__(256, 2)
void node_kernel(const float* __restrict__ nfeats,
                 const float* __restrict__ W_msg, const float* __restrict__ b_msg,
                 const float* __restrict__ W_apply, const float* __restrict__ b_apply,
                 float* __restrict__ out) {
    extern __shared__ float sm[];
    float* WmT = sm;                      // [128][64]
    float* WaT = sm + 128 * 64;           // [128][64]
    float* zb = sm + 2 * 128 * 64;        // WPB * [128][ZSTRIDE]

    int tid = threadIdx.x;
    int lane = tid & 31;
    int wid = tid >> 5;

    for (int i = tid; i < 64 * 128; i += 256) {
        int o = i >> 7, k = i & 127;
        WmT[k * 64 + o] = W_msg[i];
        WaT[k * 64 + o] = W_apply[i];
    }
    __syncthreads();

    float* z = zb + wid * (128 * ZSTRIDE);
    int base = blockIdx.x * NPB + wid * NPW;

    #pragma unroll
    for (int j = 0; j < NPW; j++) {
        int v = base + j;
        if (v >= N_NODES) v = N_NODES - 1;
        const float* sn = g_Sn + (size_t)v * D;
        const float* se = g_Se + (size_t)v * D;
        z[(lane)      * ZSTRIDE + j] = sn[lane];
        z[(lane + 32) * ZSTRIDE + j] = sn[lane + 32];
        z[(lane + 64) * ZSTRIDE + j] = se[lane];
        z[(lane + 96) * ZSTRIDE + j] = se[lane + 32];
    }
    __syncwarp();

    unsigned long long acc[2][4];
    #pragma unroll
    for (int g = 0; g < 2; g++)
        #pragma unroll
        for (int p = 0; p < 4; p++) acc[g][p] = 0ull;

    #pragma unroll 4
    for (int k = 0; k < 128; k++) {
        float w0 = WmT[k * 64 + lane];
        float w1 = WmT[k * 64 + lane + 32];
        unsigned long long w0p, w1p;
        PACK2(w0p, w0);
        PACK2(w1p, w1);
        const unsigned long long* zr = (const unsigned long long*)(z + k * ZSTRIDE);
        #pragma unroll
        for (int p = 0; p < 4; p++) {
            unsigned long long s2 = zr[p];
            FMA2(acc[0][p], w0p, s2);
            FMA2(acc[1][p], w1p, s2);
        }
    }
    __syncwarp();

    float bm0 = b_msg[lane], bm1 = b_msg[lane + 32];
    #pragma unroll
    for (int p = 0; p < 4; p++) {
        int v0 = base + 2 * p, v1 = base + 2 * p + 1;
        int c0 = v0 < N_NODES ? v0 : N_NODES - 1;
        int c1 = v1 < N_NODES ? v1 : N_NODES - 1;
        float d0 = (float)g_count[c0];
        float d1 = (float)g_count[c1];
        float i0 = d0 > 0.f ? 1.f / d0 : 0.f;
        float i1 = d1 > 0.f ? 1.f / d1 : 0.f;
        unsigned ux, uy;
        UNPACK2(ux, uy, acc[0][p]);
        float a0x = __uint_as_float(ux), a0y = __uint_as_float(uy);
        UNPACK2(ux, uy, acc[1][p]);
        float a1x = __uint_as_float(ux), a1y = __uint_as_float(uy);
        z[(64 + lane) * ZSTRIDE + 2 * p]     = d0 > 0.f ? a0x * i0 + bm0 : 0.f;
        z[(64 + lane) * ZSTRIDE + 2 * p + 1] = d1 > 0.f ? a0y * i1 + bm0 : 0.f;
        z[(96 + lane) * ZSTRIDE + 2 * p]     = d0 > 0.f ? a1x * i0 + bm1 : 0.f;
        z[(96 + lane) * ZSTRIDE + 2 * p + 1] = d1 > 0.f ? a1y * i1 + bm1 : 0.f;
    }
    #pragma unroll
    for (int j = 0; j < NPW; j++) {
        int v = base + j;
        if (v >= N_NODES) v = N_NODES - 1;
        const float* nf = nfeats + (size_t)v * D;
        z[(lane)      * ZSTRIDE + j] = nf[lane];
        z[(lane + 32) * ZSTRIDE + j] = nf[lane + 32];
    }
    __syncwarp();

    #pragma unroll
    for (int g = 0; g < 2; g++)
        #pragma unroll
        for (int p = 0; p < 4; p++) acc[g][p] = 0ull;

    #pragma unroll 4
    for (int k = 0; k < 128; k++) {
        float w0 = WaT[k * 64 + lane];
        float w1 = WaT[k * 64 + lane + 32];
        unsigned long long w0p, w1p;
        PACK2(w0p, w0);
        PACK2(w1p, w1);
        const unsigned long long* zr = (const unsigned long long*)(z + k * ZSTRIDE);
        #pragma unroll
        for (int p = 0; p < 4; p++) {
            unsigned long long s2 = zr[p];
            FMA2(acc[0][p], w0p, s2);
            FMA2(acc[1][p], w1p, s2);
        }
    }

    float ba0 = b_apply[lane], ba1 = b_apply[lane + 32];
    #pragma unroll
    for (int p = 0; p < 4; p++) {
        int v0 = base + 2 * p, v1 = base + 2 * p + 1;
        unsigned ux, uy;
        UNPACK2(ux, uy, acc[0][p]);
        float a0x = __uint_as_float(ux), a0y = __uint_as_float(uy);
        UNPACK2(ux, uy, acc[1][p]);
        float a1x = __uint_as_float(ux), a1y = __uint_as_float(uy);
        if (v0 < N_NODES) {
            out[(size_t)v0 * D + lane]      = fmaxf(a0x + ba0, 0.f);
            out[(size_t)v0 * D + lane + 32] = fmaxf(a1x + ba1, 0.f);
        }
        if (v1 < N_NODES) {
            out[(size_t)v1 * D + lane]      = fmaxf(a0y + ba0, 0.f);
            out[(size_t)v1 * D + lane + 32] = fmaxf(a1y + ba1, 0.f);
        }
    }
}

// ---------------------------------------------------------------------------
#define NODE_SMEM ((2 * 128 * 64 + WPB * 128 * ZSTRIDE) * (int)sizeof(float))

extern "C" void kernel_launch(void* const* d_in, const int* in_sizes, int n_in,
                              void* d_out, int out_size) {
    const float* nfeats  = (const float*)d_in[0];
    const float* efeats  = (const float*)d_in[1];
    const int*   src     = (const int*)d_in[2];
    const int*   dst     = (const int*)d_in[3];
    const float* W_msg   = (const float*)d_in[4];
    const float* b_msg   = (const float*)d_in[5];
    const float* W_apply = (const float*)d_in[6];
    const float* b_apply = (const float*)d_in[7];
    float* out = (float*)d_out;
    int E = in_sizes[2];

    cudaFuncSetAttribute(node_kernel, cudaFuncAttributeMaxDynamicSharedMemorySize,
                         NODE_SMEM);

    zero_counts<<<(N_NODES + 255) / 256, 256>>>();
    hist_kernel<<<(E + 255) / 256, 256>>>(dst, E);
    scan_kernel<<<1, 1024>>>();
    scatter_kernel<<<(E + 255) / 256, 256>>>(src, dst, E);
    int gblocks = (N_NODES * 32 + 255) / 256;
    gather_kernel<<<gblocks, 256>>>(nfeats, efeats);
    int nblocks = (N_NODES + NPB - 1) / NPB;
    node_kernel<<<nblocks, 256, NODE_SMEM>>>(nfeats, W_msg, b_msg, W_apply,
                                             b_apply, out);
}

// round 6
// speedup vs baseline: 1.4551x; 1.0175x over previous
#include <cuda_runtime.h>
#include <cstdint>

#define N_NODES 50000
#define MAXE    800000
#define D       64

// ---- scratch (device globals; no allocation allowed) ----
__device__ float g_Sn[N_NODES * D];   // sum of nfeats[src] per dst
__device__ float g_Se[N_NODES * D];   // sum of efeats per dst
__device__ int   g_count[N_NODES];    // in-degree
__device__ int   g_off[N_NODES];      // CSR offsets (exclusive scan)
__device__ int   g_rank[MAXE];        // within-dst rank of each edge
__device__ int2  g_edges[MAXE];       // dst-sorted (edge_id, src) records

// ---------------------------------------------------------------------------
// K1: zero degree counters
// ---------------------------------------------------------------------------
__global__ void zero_counts() {
    int i = blockIdx.x * blockDim.x + threadIdx.x;
    if (i < N_NODES) g_count[i] = 0;
}

// ---------------------------------------------------------------------------
// K2: histogram of dst; the atomic's return value is the edge's rank
// ---------------------------------------------------------------------------
__global__ void hist_kernel(const int* __restrict__ dst, int E) {
    int e = blockIdx.x * blockDim.x + threadIdx.x;
    if (e < E) g_rank[e] = atomicAdd(&g_count[dst[e]], 1);
}

// ---------------------------------------------------------------------------
// K3: single-block exclusive scan of 50K counts -> g_off (MLP via unroll)
// ---------------------------------------------------------------------------
__global__ void scan_kernel() {
    __shared__ int warp_tot[32];
    int t = threadIdx.x;
    int lane = t & 31, w = t >> 5;
    const int CHUNK = (N_NODES + 1023) / 1024;
    int begin = t * CHUNK;
    int end = begin + CHUNK;
    if (end > N_NODES) end = N_NODES;
    if (begin > N_NODES) begin = N_NODES;

    int s = 0;
    #pragma unroll 8
    for (int i = begin; i < end; i++) s += __ldg(&g_count[i]);

    int pre = s;
    #pragma unroll
    for (int d = 1; d < 32; d <<= 1) {
        int v = __shfl_up_sync(0xffffffffu, pre, d);
        if (lane >= d) pre += v;
    }
    if (lane == 31) warp_tot[w] = pre;
    __syncthreads();
    if (w == 0) {
        int v = warp_tot[lane];
        #pragma unroll
        for (int d = 1; d < 32; d <<= 1) {
            int u = __shfl_up_sync(0xffffffffu, v, d);
            if (lane >= d) v += u;
        }
        warp_tot[lane] = v;
    }
    __syncthreads();
    int base = (w > 0 ? warp_tot[w - 1] : 0) + (pre - s);
    int run = base;
    #pragma unroll 8
    for (int i = begin; i < end; i++) {
        int c = __ldg(&g_count[i]);
        g_off[i] = run;
        run += c;
    }
}

// ---------------------------------------------------------------------------
// K4: atomic-free scatter: slot = off[dst] + rank[e]
// ---------------------------------------------------------------------------
__global__ void scatter_kernel(const int* __restrict__ src,
                               const int* __restrict__ dst, int E) {
    int e = blockIdx.x * blockDim.x + threadIdx.x;
    if (e >= E) return;
    int d = dst[e];
    int slot = g_off[d] + g_rank[e];
    g_edges[slot] = make_int2(e, src[e]);
}

// ---------------------------------------------------------------------------
// K5: atomic-free gather-sum. One warp per node.
// Edge records: one coalesced LDG.64 per lane per 32-chunk, then broadcast
// via shfl (no SMEM, no syncwarp, no LDS->LDG dependency). Unroll 8 -> MLP 8.
// lanes 0..15: chunk q of sum(nfeats[src]); lanes 16..31: chunk q of sum(efeats)
// ---------------------------------------------------------------------------
#define ACC4(A, T) {A.x += T.x; A.y += T.y; A.z += T.z; A.w += T.w;}
__global__ __launch_bounds__(256)
void gather_kernel(const float* __restrict__ nfeats,
                   const float* __restrict__ efeats) {
    int v = (blockIdx.x * blockDim.x + threadIdx.x) >> 5;
    int lane = threadIdx.x & 31;
    if (v >= N_NODES) return;
    int start = g_off[v];
    int cnt = g_count[v];
    int q = lane & 15;
    bool isN = lane < 16;
    const float* fbase = isN ? nfeats : efeats;

    float4 acc0 = make_float4(0.f, 0.f, 0.f, 0.f);
    float4 acc1 = make_float4(0.f, 0.f, 0.f, 0.f);

    for (int base = 0; base < cnt; base += 32) {
        int n = cnt - base;
        if (n > 32) n = 32;
        int2 rec = make_int2(0, 0);
        if (lane < n) rec = __ldg(&g_edges[start + base + lane]);
        int j = 0;
        for (; j + 8 <= n; j += 8) {
            int idx[8];
            #pragma unroll
            for (int u = 0; u < 8; u++) {
                int x = __shfl_sync(0xffffffffu, rec.x, j + u);
                int y = __shfl_sync(0xffffffffu, rec.y, j + u);
                idx[u] = isN ? y : x;
            }
            float4 t[8];
            #pragma unroll
            for (int u = 0; u < 8; u++)
                t[u] = __ldg((const float4*)(fbase + (size_t)idx[u] * D) + q);
            #pragma unroll
            for (int u = 0; u < 8; u += 2) {
                ACC4(acc0, t[u]);
                ACC4(acc1, t[u + 1]);
            }
        }
        for (; j + 2 <= n; j += 2) {
            int x0 = __shfl_sync(0xffffffffu, rec.x, j);
            int y0 = __shfl_sync(0xffffffffu, rec.y, j);
            int x1 = __shfl_sync(0xffffffffu, rec.x, j + 1);
            int y1 = __shfl_sync(0xffffffffu, rec.y, j + 1);
            float4 a = __ldg((const float4*)(fbase + (size_t)(isN ? y0 : x0) * D) + q);
            float4 b = __ldg((const float4*)(fbase + (size_t)(isN ? y1 : x1) * D) + q);
            ACC4(acc0, a);
            ACC4(acc1, b);
        }
        if (j < n) {
            int x0 = __shfl_sync(0xffffffffu, rec.x, j);
            int y0 = __shfl_sync(0xffffffffu, rec.y, j);
            float4 a = __ldg((const float4*)(fbase + (size_t)(isN ? y0 : x0) * D) + q);
            ACC4(acc0, a);
        }
    }
    acc0.x += acc1.x; acc0.y += acc1.y; acc0.z += acc1.z; acc0.w += acc1.w;
    float* outp = (isN ? g_Sn : g_Se) + (size_t)v * D + q * 4;
    *(float4*)outp = acc0;
}

// ---------------------------------------------------------------------------
// K6: node update (fused msg-GEMM + mean + apply-GEMM + relu).
// Weights staged PAIRED: Wp[k][o&31] = (W[o], W[o+32]) -> one LDS.64/k.
// z staged transposed with ZSTRIDE=12 (48B rows, 16B-aligned) -> 2 LDS.128/k.
// ---------------------------------------------------------------------------
#define ZSTRIDE 12
#define WPB 8
#define NPW 8
#define NPB (WPB * NPW)

#define PACK2(dst, f) asm("mov.b64 %0, {%1,%1};" : "=l"(dst) : "r"(__float_as_uint(f)))
#define UNPACK2(lo, hi, src) asm("mov.b64 {%0,%1}, %2;" : "=r"(lo), "=r"(hi) : "l"(src))
#define FMA2(acc, a, b) asm("fma.rn.f32x2 %0, %1, %2, %0;" : "+l"(acc) : "l"(a), "l"(b))

__global__ __launch_bounds__(256, 2)
void node_kernel(const float* __restrict__ nfeats,
                 const float* __restrict__ W_msg, const float* __restrict__ b_msg,
                 const float* __restrict__ W_apply, const float* __restrict__ b_apply,
                 float* __restrict__ out) {
    extern __shared__ float sm[];
    float* WmT = sm;                      // [128][32 pairs] = 64 floats/row
    float* WaT = sm + 128 * 64;
    float* zb = sm + 2 * 128 * 64;        // WPB * [128][ZSTRIDE]

    int tid = threadIdx.x;
    int lane = tid & 31;
    int wid = tid >> 5;

    // Stage weights paired: row k, pair index o&31, component o>>5
    for (int i = tid; i < 64 * 128; i += 256) {
        int o = i >> 7, k = i & 127;
        int slot = k * 64 + (o & 31) * 2 + (o >> 5);
        WmT[slot] = W_msg[i];
        WaT[slot] = W_apply[i];
    }
    __syncthreads();

    float* z = zb + wid * (128 * ZSTRIDE);
    int base = blockIdx.x * NPB + wid * NPW;

    // Phase A setup: rows 0..63 = Sn, rows 64..127 = Se
    #pragma unroll
    for (int j = 0; j < NPW; j++) {
        int v = base + j;
        if (v >= N_NODES) v = N_NODES - 1;
        const float* sn = g_Sn + (size_t)v * D;
        const float* se = g_Se + (size_t)v * D;
        z[(lane)      * ZSTRIDE + j] = sn[lane];
        z[(lane + 32) * ZSTRIDE + j] = sn[lane + 32];
        z[(lane + 64) * ZSTRIDE + j] = se[lane];
        z[(lane + 96) * ZSTRIDE + j] = se[lane + 32];
    }
    __syncwarp();

    unsigned long long acc[2][4];
    #pragma unroll
    for (int g = 0; g < 2; g++)
        #pragma unroll
        for (int p = 0; p < 4; p++) acc[g][p] = 0ull;

    #pragma unroll 4
    for (int k = 0; k < 128; k++) {
        float2 wp = ((const float2*)(WmT + k * 64))[lane];
        unsigned long long w0p, w1p;
        PACK2(w0p, wp.x);
        PACK2(w1p, wp.y);
        ulonglong2 za = *(const ulonglong2*)(z + k * ZSTRIDE);
        ulonglong2 zc = *(const ulonglong2*)(z + k * ZSTRIDE + 4);
        FMA2(acc[0][0], w0p, za.x);
        FMA2(acc[1][0], w1p, za.x);
        FMA2(acc[0][1], w0p, za.y);
        FMA2(acc[1][1], w1p, za.y);
        FMA2(acc[0][2], w0p, zc.x);
        FMA2(acc[1][2], w1p, zc.x);
        FMA2(acc[0][3], w0p, zc.y);
        FMA2(acc[1][3], w1p, zc.y);
    }
    __syncwarp();

    // h_neigh + rebuild z for Phase B
    float bm0 = b_msg[lane], bm1 = b_msg[lane + 32];
    #pragma unroll
    for (int p = 0; p < 4; p++) {
        int v0 = base + 2 * p, v1 = base + 2 * p + 1;
        int c0 = v0 < N_NODES ? v0 : N_NODES - 1;
        int c1 = v1 < N_NODES ? v1 : N_NODES - 1;
        float d0 = (float)g_count[c0];
        float d1 = (float)g_count[c1];
        float i0 = d0 > 0.f ? 1.f / d0 : 0.f;
        float i1 = d1 > 0.f ? 1.f / d1 : 0.f;
        unsigned ux, uy;
        UNPACK2(ux, uy, acc[0][p]);
        float a0x = __uint_as_float(ux), a0y = __uint_as_float(uy);
        UNPACK2(ux, uy, acc[1][p]);
        float a1x = __uint_as_float(ux), a1y = __uint_as_float(uy);
        z[(64 + lane) * ZSTRIDE + 2 * p]     = d0 > 0.f ? a0x * i0 + bm0 : 0.f;
        z[(64 + lane) * ZSTRIDE + 2 * p + 1] = d1 > 0.f ? a0y * i1 + bm0 : 0.f;
        z[(96 + lane) * ZSTRIDE + 2 * p]     = d0 > 0.f ? a1x * i0 + bm1 : 0.f;
        z[(96 + lane) * ZSTRIDE + 2 * p + 1] = d1 > 0.f ? a1y * i1 + bm1 : 0.f;
    }
    #pragma unroll
    for (int j = 0; j < NPW; j++) {
        int v = base + j;
        if (v >= N_NODES) v = N_NODES - 1;
        const float* nf = nfeats + (size_t)v * D;
        z[(lane)      * ZSTRIDE + j] = nf[lane];
        z[(lane + 32) * ZSTRIDE + j] = nf[lane + 32];
    }
    __syncwarp();

    #pragma unroll
    for (int g = 0; g < 2; g++)
        #pragma unroll
        for (int p = 0; p < 4; p++) acc[g][p] = 0ull;

    #pragma unroll 4
    for (int k = 0; k < 128; k++) {
        float2 wp = ((const float2*)(WaT + k * 64))[lane];
        unsigned long long w0p, w1p;
        PACK2(w0p, wp.x);
        PACK2(w1p, wp.y);
        ulonglong2 za = *(const ulonglong2*)(z + k * ZSTRIDE);
        ulonglong2 zc = *(const ulonglong2*)(z + k * ZSTRIDE + 4);
        FMA2(acc[0][0], w0p, za.x);
        FMA2(acc[1][0], w1p, za.x);
        FMA2(acc[0][1], w0p, za.y);
        FMA2(acc[1][1], w1p, za.y);
        FMA2(acc[0][2], w0p, zc.x);
        FMA2(acc[1][2], w1p, zc.x);
        FMA2(acc[0][3], w0p, zc.y);
        FMA2(acc[1][3], w1p, zc.y);
    }

    float ba0 = b_apply[lane], ba1 = b_apply[lane + 32];
    #pragma unroll
    for (int p = 0; p < 4; p++) {
        int v0 = base + 2 * p, v1 = base + 2 * p + 1;
        unsigned ux, uy;
        UNPACK2(ux, uy, acc[0][p]);
        float a0x = __uint_as_float(ux), a0y = __uint_as_float(uy);
        UNPACK2(ux, uy, acc[1][p]);
        float a1x = __uint_as_float(ux), a1y = __uint_as_float(uy);
        if (v0 < N_NODES) {
            out[(size_t)v0 * D + lane]      = fmaxf(a0x + ba0, 0.f);
            out[(size_t)v0 * D + lane + 32] = fmaxf(a1x + ba1, 0.f);
        }
        if (v1 < N_NODES) {
            out[(size_t)v1 * D + lane]      = fmaxf(a0y + ba0, 0.f);
            out[(size_t)v1 * D + lane + 32] = fmaxf(a1y + ba1, 0.f);
        }
    }
}

// ---------------------------------------------------------------------------
#define NODE_SMEM ((2 * 128 * 64 + WPB * 128 * ZSTRIDE) * (int)sizeof(float))

extern "C" void kernel_launch(void* const* d_in, const int* in_sizes, int n_in,
                              void* d_out, int out_size) {
    const float* nfeats  = (const float*)d_in[0];
    const float* efeats  = (const float*)d_in[1];
    const int*   src     = (const int*)d_in[2];
    const int*   dst     = (const int*)d_in[3];
    const float* W_msg   = (const float*)d_in[4];
    const float* b_msg   = (const float*)d_in[5];
    const float* W_apply = (const float*)d_in[6];
    const float* b_apply = (const float*)d_in[7];
    float* out = (float*)d_out;
    int E = in_sizes[2];

    cudaFuncSetAttribute(node_kernel, cudaFuncAttributeMaxDynamicSharedMemorySize,
                         NODE_SMEM);

    zero_counts<<<(N_NODES + 255) / 256, 256>>>();
    hist_kernel<<<(E + 255) / 256, 256>>>(dst, E);
    scan_kernel<<<1, 1024>>>();
    scatter_kernel<<<(E + 255) / 256, 256>>>(src, dst, E);
    int gblocks = (N_NODES * 32 + 255) / 256;
    gather_kernel<<<gblocks, 256>>>(nfeats, efeats);
    int nblocks = (N_NODES + NPB - 1) / NPB;
    node_kernel<<<nblocks, 256, NODE_SMEM>>>(nfeats, W_msg, b_msg, W_apply,
                                             b_apply, out);
}